// round 11
// baseline (speedup 1.0000x reference)
#include <cuda_runtime.h>

#define BB   32
#define TT   4096
#define DD   512
#define GG   8
#define OO   512
#define CHUNK 128
#define NCHUNK (TT/CHUNK)   // 32

// Scratch (__device__ globals; no allocations allowed)
__device__ float d_sums[BB*GG*DD];
__device__ int   d_counts[BB*GG];
__device__ int   d_st[TT];      // token ids, group-sorted (shared across b)
__device__ int   d_sg[TT];      // group id per sorted slot

// ---------------------------------------------------------------- zero
__global__ void __launch_bounds__(256) k_zero() {
    int i = blockIdx.x * 256 + threadIdx.x;
    ((float4*)d_sums)[i] = make_float4(0.f,0.f,0.f,0.f);
    if (blockIdx.x == 0 && threadIdx.x < BB*GG) d_counts[threadIdx.x] = 0;
}

// ---------------------------------------------------------------- sort
// 1 CTA, 8 warps. Warp g scans all TT token types (16 KB, L1-resident after
// first pass) and ballot-compacts its group's token ids. No atomics.
__global__ void __launch_bounds__(256) k_sort(const int* __restrict__ tt) {
    __shared__ int s_cnt[GG];
    int tid  = threadIdx.x;
    int lane = tid & 31;
    int w    = tid >> 5;          // warp == group

    int c = 0;
    #pragma unroll 4
    for (int t0 = 0; t0 < TT; t0 += 32)
        c += (tt[t0 + lane] == w);
    #pragma unroll
    for (int off = 16; off > 0; off >>= 1)
        c += __shfl_down_sync(0xffffffffu, c, off);
    if (lane == 0) s_cnt[w] = c;
    __syncthreads();

    int base = 0;
    #pragma unroll
    for (int g = 0; g < GG; g++) base += (g < w) ? s_cnt[g] : 0;

    int pos = base;
    for (int t0 = 0; t0 < TT; t0 += 32) {
        int g = tt[t0 + lane];
        unsigned m = __ballot_sync(0xffffffffu, g == w);
        if (g == w) {
            int r = __popc(m & ((1u << lane) - 1u));
            d_st[pos + r] = t0 + lane;
            d_sg[pos + r] = w;
        }
        pos += __popc(m);
    }
}

// ------------------------------------------------------------- masked sums
// grid (NCHUNK, BB), 256 threads (R4-measured-best variant). Warp-uniform
// predicated loads, 8-wide front-batched; atomic flush at group boundaries.
__device__ __forceinline__ void flush_acc(int b, int g, int lane, float4 a) {
    float* dst = &d_sums[((size_t)b*GG + g)*DD + lane*4];
    atomicAdd(dst+0, a.x); atomicAdd(dst+1, a.y);
    atomicAdd(dst+2, a.z); atomicAdd(dst+3, a.w);
}

__global__ void __launch_bounds__(256) k_main(const float* __restrict__ batch,
                                              const int* __restrict__ pad) {
    __shared__ int s_tok[CHUNK];
    __shared__ int s_grp[CHUNK];
    __shared__ int s_val[CHUNK];

    int b   = blockIdx.y;
    int c0  = blockIdx.x * CHUNK;
    int tid = threadIdx.x;

    if (tid < CHUNK) {
        int t = d_st[c0 + tid];
        s_tok[tid] = t;
        s_grp[tid] = d_sg[c0 + tid];
        s_val[tid] = pad[(size_t)b*TT + t] ? 0 : 1;   // bool -> int32 transport
    }
    __syncthreads();

    // per-(b,g) valid counts: 64 threads, 16 smem reads each
    if (tid < 64) {
        int g = tid >> 3, j = tid & 7;
        int c = 0;
        #pragma unroll
        for (int k = 0; k < 16; k++) {
            int i = j*16 + k;
            c += (s_grp[i] == g) & s_val[i];
        }
        if (c) atomicAdd(&d_counts[b*GG + g], c);
    }

    int lane = tid & 127;
    int half = tid >> 7;
    const float4* bb = (const float4*)(batch + (size_t)b * TT * DD);

    float4 acc = make_float4(0.f,0.f,0.f,0.f);
    int curg = s_grp[0];

    #define PLOAD(V, J)                                                     \
        float4 V = make_float4(0.f,0.f,0.f,0.f);                            \
        if (s_val[i + 2*(J)])                                               \
            V = __ldcs(&bb[(size_t)s_tok[i + 2*(J)] * (DD/4) + lane]);

    #define ACCSTEP(J, V)                                                   \
        { int g_ = s_grp[i + 2*(J)];                                        \
          if (g_ != curg) {                                                 \
              flush_acc(b, curg, lane, acc);                                \
              acc = make_float4(0.f,0.f,0.f,0.f); curg = g_; }              \
          acc.x += (V).x; acc.y += (V).y; acc.z += (V).z; acc.w += (V).w; }

    #pragma unroll
    for (int s = 0; s < 8; s++) {
        int i = half + s*16;
        PLOAD(v0, 0) PLOAD(v1, 1) PLOAD(v2, 2) PLOAD(v3, 3)
        PLOAD(v4, 4) PLOAD(v5, 5) PLOAD(v6, 6) PLOAD(v7, 7)
        ACCSTEP(0, v0); ACCSTEP(1, v1); ACCSTEP(2, v2); ACCSTEP(3, v3);
        ACCSTEP(4, v4); ACCSTEP(5, v5); ACCSTEP(6, v6); ACCSTEP(7, v7);
    }
    flush_acc(b, curg, lane, acc);
    #undef PLOAD
    #undef ACCSTEP
}

// ------------------------------------------------------ means -> GEMM + bias
// grid (8 g, 16 o-blocks of 32, 2 b-halves of 16) = 256 CTAs, 512 threads,
// 80 KB dynamic smem -> 2 CTAs/SM (32 warps/SM of latency hiding).
// warp = one d-slice of 32 (d warp-uniform), lanes = 32 consecutive o.
// Phase 1: transpose-divide 16 means into smem [d][b16] (pad 20).
// Phase 2: 2x16 front-batched W loads into regs, 512 FFMAs vs broadcast
//          LDS.128 mean reads.
// Phase 3: slice reduction via padded smem, coalesced STG + bias.
#define GOB  32              // o per CTA
#define NSL  16              // d-slices (= warps)
#define SLD  (DD/NSL)        // 32 d per slice
#define HB   16              // b-rows per CTA
#define MTP  20              // padded b-row (80 B, 16B-aligned)
#define GEMM_SMEM ((DD*MTP + NSL*GOB*MTP) * 4)   // 40960+40960 = 81920 B

__global__ void __launch_bounds__(512, 2) k_gemm(const float* __restrict__ W,
                                                 const float* __restrict__ bias,
                                                 float* __restrict__ out) {
    extern __shared__ float sm[];
    float* s_mt  = sm;               // [512][20]  means^T: [d][b16]
    float* s_red = sm + DD*MTP;      // [16][32][20] slice partials

    __shared__ float s_inv[HB];

    int g   = blockIdx.x;
    int o0  = blockIdx.y * GOB;
    int b0  = blockIdx.z * HB;
    int tid = threadIdx.x;

    if (tid < HB) {
        int c = d_counts[(b0 + tid)*GG + g];
        s_inv[tid] = (c > 0) ? 1.0f / (float)c : 0.0f;
    }
    __syncthreads();

    // transpose-divide: 16b x 512d, coalesced loads
    for (int idx = tid; idx < HB*DD; idx += 512) {
        int b = idx >> 9;
        int d = idx & (DD-1);
        float s = d_sums[((size_t)(b0 + b)*GG + g)*DD + d];
        s_mt[d*MTP + b] = s * s_inv[b];
    }
    __syncthreads();

    int o  = tid & 31;          // lane -> output column
    int sl = tid >> 5;          // warp -> d-slice
    int d0 = sl * SLD;

    const float* wp = W + ((size_t)g*DD + d0)*OO + o0 + o;

    float acc[HB];
    #pragma unroll
    for (int b = 0; b < HB; b++) acc[b] = 0.f;

    #pragma unroll
    for (int h = 0; h < 2; h++) {
        // front-batched W half-strip: 16 coalesced LDG.32
        float wreg[SLD/2];
        #pragma unroll
        for (int k = 0; k < SLD/2; k++)
            wreg[k] = __ldg(wp + (size_t)(h*(SLD/2) + k)*OO);

        #pragma unroll
        for (int k = 0; k < SLD/2; k++) {
            const float4* mrow =
                (const float4*)(s_mt + (d0 + h*(SLD/2) + k)*MTP);
            float w = wreg[k];
            #pragma unroll
            for (int j = 0; j < 4; j++) {
                float4 m = mrow[j];                    // broadcast LDS.128
                acc[j*4+0] = fmaf(m.x, w, acc[j*4+0]);
                acc[j*4+1] = fmaf(m.y, w, acc[j*4+1]);
                acc[j*4+2] = fmaf(m.z, w, acc[j*4+2]);
                acc[j*4+3] = fmaf(m.w, w, acc[j*4+3]);
            }
        }
    }

    // stash slice partials: [sl][o][b16], padded row
    float* rp = s_red + (sl*GOB + o)*MTP;
    #pragma unroll
    for (int j = 0; j < 4; j++)
        ((float4*)rp)[j] = make_float4(acc[j*4], acc[j*4+1],
                                       acc[j*4+2], acc[j*4+3]);
    __syncthreads();

    // reduce 16 slices; consecutive threads = consecutive o -> coalesced STG
    {
        int oo = tid & 31;
        int b  = tid >> 5;
        float s = 0.f;
        #pragma unroll
        for (int sl2 = 0; sl2 < NSL; sl2++)
            s += s_red[(sl2*GOB + oo)*MTP + b];
        out[((size_t)(b0 + b)*GG + g)*OO + o0 + oo] =
            s + bias[(size_t)g*OO + o0 + oo];
    }
}

// ---------------------------------------------------------------- launcher
// metadata order: batch(f32), W(f32), b_bias(f32), token_types(i32),
//                 key_padding_mask(bool -> int32)
extern "C" void kernel_launch(void* const* d_in, const int* in_sizes, int n_in,
                              void* d_out, int out_size) {
    const float* batch = (const float*)d_in[0];
    const float* W     = (const float*)d_in[1];
    const float* bias  = (const float*)d_in[2];
    const int*   tt    = (const int*)d_in[3];
    const int*   pad   = (const int*)d_in[4];
    float* out = (float*)d_out;

    cudaFuncSetAttribute(k_gemm, cudaFuncAttributeMaxDynamicSharedMemorySize,
                         GEMM_SMEM);

    k_zero<<<BB*GG*DD/(256*4), 256>>>();
    k_sort<<<1, 256>>>(tt);

    dim3 gmain(NCHUNK, BB);
    k_main<<<gmain, 256>>>(batch, pad);

    dim3 ggemm(GG, OO/GOB, BB/HB);
    k_gemm<<<ggemm, 512, GEMM_SMEM>>>(W, bias, out);
}